// round 1
// baseline (speedup 1.0000x reference)
#include <cuda_runtime.h>
#include <cuda_bf16.h>
#include <mma.h>

using namespace nvcuda;

// Problem constants (fixed by the reference)
constexpr int D_MODEL   = 1024;
constexpr int NUM_HEADS = 16;
constexpr int HEAD_DIM  = 64;
constexpr int BATCH     = 4;
constexpr int SEQ       = 4096;
constexpr int M_TOK     = BATCH * SEQ;   // 16384 tokens

// Scratch (device globals: allocation-free, graph-capture safe)
__device__ float g_Q[M_TOK * D_MODEL];
__device__ float g_K[M_TOK * D_MODEL];
__device__ float g_V[M_TOK * D_MODEL];
__device__ float g_X[M_TOK * D_MODEL];

// ---------------------------------------------------------------------------
// GEMM: C[M,N] = A[M,K] @ W[N,K]^T + bias[N]   (K = N = 1024 fixed)
// tf32x3 split for ~fp32 accuracy on tensor cores.
// Block tile 128x64, K-tile 32, 8 warps (4x2), warp tile 32x32 (2x2 wmma 16x16x8)
// ---------------------------------------------------------------------------
constexpr int BM = 128, BN = 64, BK = 32;
constexpr int LDS_K = BK + 4;   // 36, padded smem row (multiple of 4 for wmma)
constexpr int LDS_C = BN + 4;   // 68, epilogue smem row
constexpr int SMEM_FLOATS = BM * LDS_C;  // 8704 floats = 34 KB (>= A+B tiles)

using FragA = wmma::fragment<wmma::matrix_a, 16, 16, 8, wmma::precision::tf32, wmma::row_major>;
using FragB = wmma::fragment<wmma::matrix_b, 16, 16, 8, wmma::precision::tf32, wmma::col_major>;
using FragC = wmma::fragment<wmma::accumulator, 16, 16, 8, float>;

__device__ __forceinline__ void split_tf32_a(const FragA& raw, FragA& hi, FragA& lo) {
#pragma unroll
    for (int i = 0; i < raw.num_elements; i++) {
        float x = raw.x[i];
        float h = wmma::__float_to_tf32(x);
        hi.x[i] = h;
        lo.x[i] = wmma::__float_to_tf32(x - h);
    }
}
__device__ __forceinline__ void split_tf32_b(const FragB& raw, FragB& hi, FragB& lo) {
#pragma unroll
    for (int i = 0; i < raw.num_elements; i++) {
        float x = raw.x[i];
        float h = wmma::__float_to_tf32(x);
        hi.x[i] = h;
        lo.x[i] = wmma::__float_to_tf32(x - h);
    }
}

__global__ void __launch_bounds__(256)
gemm_tf32x3_bias(const float* __restrict__ A,
                 const float* __restrict__ W,
                 const float* __restrict__ bias,
                 float* __restrict__ C)
{
    __shared__ __align__(16) float smem[SMEM_FLOATS];
    float* As = smem;                 // [128][36]
    float* Bs = smem + BM * LDS_K;    // [64][36]

    const int tid  = threadIdx.x;
    const int warp = tid >> 5;
    const int wm   = warp >> 1;       // 0..3 -> 32 rows each
    const int wn   = warp & 1;        // 0..1 -> 32 cols each
    const int m0   = blockIdx.y * BM;
    const int n0   = blockIdx.x * BN;

    FragC acc[2][2];
#pragma unroll
    for (int i = 0; i < 2; i++)
#pragma unroll
        for (int j = 0; j < 2; j++)
            wmma::fill_fragment(acc[i][j], 0.0f);

    for (int kt = 0; kt < D_MODEL; kt += BK) {
        // Load A tile (128x32): 1024 float4 over 256 threads
#pragma unroll
        for (int p = 0; p < 4; p++) {
            int idx = tid + p * 256;
            int r = idx >> 3, c = idx & 7;
            float4 v = *(const float4*)(A + (size_t)(m0 + r) * D_MODEL + kt + c * 4);
            *(float4*)(As + r * LDS_K + c * 4) = v;
        }
        // Load B tile (64x32): 512 float4
#pragma unroll
        for (int p = 0; p < 2; p++) {
            int idx = tid + p * 256;
            int r = idx >> 3, c = idx & 7;
            float4 v = *(const float4*)(W + (size_t)(n0 + r) * D_MODEL + kt + c * 4);
            *(float4*)(Bs + r * LDS_K + c * 4) = v;
        }
        __syncthreads();

#pragma unroll
        for (int kk = 0; kk < BK; kk += 8) {
            FragA a_hi[2], a_lo[2];
            FragB b_hi[2], b_lo[2];
#pragma unroll
            for (int mi = 0; mi < 2; mi++) {
                FragA raw;
                wmma::load_matrix_sync(raw, As + (wm * 32 + mi * 16) * LDS_K + kk, LDS_K);
                split_tf32_a(raw, a_hi[mi], a_lo[mi]);
            }
#pragma unroll
            for (int ni = 0; ni < 2; ni++) {
                FragB raw;
                // col-major view: element (k, n) at Bs[(n_base+n)*LDS_K + kk + k]
                wmma::load_matrix_sync(raw, Bs + (wn * 32 + ni * 16) * LDS_K + kk, LDS_K);
                split_tf32_b(raw, b_hi[ni], b_lo[ni]);
            }
#pragma unroll
            for (int mi = 0; mi < 2; mi++)
#pragma unroll
                for (int ni = 0; ni < 2; ni++) {
                    wmma::mma_sync(acc[mi][ni], a_hi[mi], b_lo[ni], acc[mi][ni]);
                    wmma::mma_sync(acc[mi][ni], a_lo[mi], b_hi[ni], acc[mi][ni]);
                    wmma::mma_sync(acc[mi][ni], a_hi[mi], b_hi[ni], acc[mi][ni]);
                }
        }
        __syncthreads();
    }

    // Epilogue: park accumulators in smem, add bias, vectorized store
    float* Cs = smem;  // [128][68]
#pragma unroll
    for (int mi = 0; mi < 2; mi++)
#pragma unroll
        for (int ni = 0; ni < 2; ni++)
            wmma::store_matrix_sync(Cs + (wm * 32 + mi * 16) * LDS_C + wn * 32 + ni * 16,
                                    acc[mi][ni], LDS_C, wmma::mem_row_major);
    __syncthreads();

    const int c4 = tid & 15;   // 16 float4 per 64-wide row
    const int r0 = tid >> 4;   // 16 row groups
    float4 bv = *(const float4*)(bias + n0 + c4 * 4);
#pragma unroll
    for (int rr = 0; rr < BM; rr += 16) {
        int r = rr + r0;
        float4 v = *(float4*)(Cs + r * LDS_C + c4 * 4);
        v.x += bv.x; v.y += bv.y; v.z += bv.z; v.w += bv.w;
        *(float4*)(C + (size_t)(m0 + r) * D_MODEL + n0 + c4 * 4) = v;
    }
}

// ---------------------------------------------------------------------------
// Per-token "attention": one block per token.
//   E[i,l] = sum_d Q[t,i*64+d]*K[t,l*64+d];  A = softmax(mask? E/32 : 0, over l)
//   X[t,i*64+d] = sum_l A[i,l]*V[t,l*64+d]
// ---------------------------------------------------------------------------
__global__ void __launch_bounds__(256)
attn_mix_kernel(const float* __restrict__ Q,
                const float* __restrict__ K,
                const float* __restrict__ V,
                const int*   __restrict__ mask,
                float* __restrict__ X)
{
    __shared__ __align__(16) float qs[D_MODEL];
    __shared__ __align__(16) float vs[D_MODEL];
    __shared__ __align__(16) float kT[D_MODEL];   // kT[d*16 + l]
    __shared__ float a_s[NUM_HEADS * NUM_HEADS];

    const int t = threadIdx.x;
    const size_t base = (size_t)blockIdx.x * D_MODEL;

    // Load token vectors (4 floats/thread)
    float4 q4 = *(const float4*)(Q + base + t * 4);
    float4 v4 = *(const float4*)(V + base + t * 4);
    float4 k4 = *(const float4*)(K + base + t * 4);
    *(float4*)(qs + t * 4) = q4;
    *(float4*)(vs + t * 4) = v4;
    {   // transpose K into kT[d][l]
        int j = t * 4;
        kT[(j & 63) * 16 + (j >> 6)]             = k4.x;
        kT[((j + 1) & 63) * 16 + ((j + 1) >> 6)] = k4.y;
        kT[((j + 2) & 63) * 16 + ((j + 2) >> 6)] = k4.z;
        kT[((j + 3) & 63) * 16 + ((j + 3) >> 6)] = k4.w;
    }
    __syncthreads();

    // 256 threads = 256 energy entries
    const int i = t >> 4, l = t & 15;
    float e = 0.0f;
#pragma unroll 8
    for (int d = 0; d < HEAD_DIM; d++)
        e += qs[i * 64 + d] * kT[d * 16 + l];

    const int mk = mask[blockIdx.x];
    e = mk ? e * 0.03125f : 0.0f;   // 1/sqrt(1024); masked -> uniform softmax

    // softmax over l (16-lane sub-groups)
    float mx = e;
#pragma unroll
    for (int off = 8; off; off >>= 1)
        mx = fmaxf(mx, __shfl_xor_sync(0xffffffffu, mx, off, 16));
    float p = expf(e - mx);
    float s = p;
#pragma unroll
    for (int off = 8; off; off >>= 1)
        s += __shfl_xor_sync(0xffffffffu, s, off, 16);
    a_s[t] = p / s;
    __syncthreads();

    // X = A @ V_heads : 4 outputs per thread, coalesced & conflict-free
#pragma unroll
    for (int r = 0; r < 4; r++) {
        int o  = r * 256 + t;
        int oi = o >> 6, od = o & 63;
        float x = 0.0f;
#pragma unroll
        for (int ll = 0; ll < 16; ll++)
            x += a_s[oi * 16 + ll] * vs[ll * 64 + od];
        X[base + o] = x;
    }
}

// ---------------------------------------------------------------------------
// Launch
// ---------------------------------------------------------------------------
extern "C" void kernel_launch(void* const* d_in, const int* in_sizes, int n_in,
                              void* d_out, int out_size)
{
    (void)in_sizes; (void)n_in; (void)out_size;
    const float* query = (const float*)d_in[0];
    const float* key   = (const float*)d_in[1];
    const float* value = (const float*)d_in[2];
    const int*   mask  = (const int*)  d_in[3];
    const float* Wq = (const float*)d_in[4];
    const float* bq = (const float*)d_in[5];
    const float* Wk = (const float*)d_in[6];
    const float* bk = (const float*)d_in[7];
    const float* Wv = (const float*)d_in[8];
    const float* bv = (const float*)d_in[9];
    const float* Wo = (const float*)d_in[10];
    const float* bo = (const float*)d_in[11];
    float* out = (float*)d_out;

    void *pQ, *pK, *pV, *pX;
    cudaGetSymbolAddress(&pQ, g_Q);
    cudaGetSymbolAddress(&pK, g_K);
    cudaGetSymbolAddress(&pV, g_V);
    cudaGetSymbolAddress(&pX, g_X);

    dim3 grid(D_MODEL / BN, M_TOK / BM);   // (16, 128)
    gemm_tf32x3_bias<<<grid, 256>>>(query, Wq, bq, (float*)pQ);
    gemm_tf32x3_bias<<<grid, 256>>>(key,   Wk, bk, (float*)pK);
    gemm_tf32x3_bias<<<grid, 256>>>(value, Wv, bv, (float*)pV);
    attn_mix_kernel<<<M_TOK, 256>>>((const float*)pQ, (const float*)pK,
                                    (const float*)pV, mask, (float*)pX);
    gemm_tf32x3_bias<<<grid, 256>>>((const float*)pX, Wo, bo, out);
}

// round 4
// speedup vs baseline: 5.9162x; 5.9162x over previous
#include <cuda_runtime.h>
#include <cuda_bf16.h>
#include <mma.h>
#include <cstdint>

// ---------------------------------------------------------------------------
// Arch-feature gate: tcgen05 is only legal in PTX targeting sm_103a/sm_100a.
// The compute_103 (no 'a') PTX pass gets a correct wmma-bf16 fallback with
// identical launch geometry and identical math.
// ---------------------------------------------------------------------------
#if defined(__CUDA_ARCH__) && \
    (defined(__CUDA_ARCH_FEAT_SM103_ALL) || defined(__CUDA_ARCH_FEAT_SM100_ALL) || \
     (defined(__CUDA_ARCH_SPECIFIC__)        && (__CUDA_ARCH_SPECIFIC__ >= 1000)) || \
     (defined(__CUDA_ARCH_FAMILY_SPECIFIC__) && (__CUDA_ARCH_FAMILY_SPECIFIC__ >= 1000)))
#define HAS_TCGEN05 1
#else
#define HAS_TCGEN05 0
#endif

// ---------------------------------------------------------------------------
// Problem constants
// ---------------------------------------------------------------------------
constexpr int D_MODEL   = 1024;
constexpr int NUM_HEADS = 16;
constexpr int HEAD_DIM  = 64;
constexpr int BATCH     = 4;
constexpr int SEQ       = 4096;
constexpr int M_TOK     = BATCH * SEQ;     // 16384 tokens
// 3-term bf16 split along K:
//   A = [a_hi | a_lo | a_hi],  B = [b_hi | b_hi | b_lo]
//   GEMM(K=3072) = a.b - a_lo.b_lo   (error ~2^-18)
constexpr int KPACK     = 3 * D_MODEL;     // 3072

// GEMM tiling (tcgen05 path)
constexpr int BM = 128;
constexpr int BN = 256;
constexpr int CHUNK_K = 64;                // bf16 elems per K chunk (128B rows, SW128)
constexpr int NCHUNK  = KPACK / CHUNK_K;   // 48
constexpr int NSTAGE  = 4;

constexpr int A_STAGE_BYTES = BM * 128;    // 16384
constexpr int B_STAGE_BYTES = BN * 128;    // 32768
constexpr int STAGE_BYTES   = A_STAGE_BYTES + B_STAGE_BYTES;  // 49152
constexpr int BAR_OFF       = NSTAGE * STAGE_BYTES;           // 196608
constexpr int SMEM_TOTAL    = BAR_OFF + 64;

constexpr int TMEM_COLS = 256;

// idesc: kind::f16, dtype=F32, atype=btype=BF16, N=256, M=128 (cg1)
constexpr uint32_t IDESC =
    (1u << 4) | (1u << 7) | (1u << 10) | ((BN / 8) << 17) | ((BM / 16) << 24);

// SW128 K-major smem descriptor base (layout=SW128, version=1, SBO=64, LBO=1)
constexpr uint64_t DESC_BASE_SW128 =
    (uint64_t(2) << 61) | (uint64_t(1) << 46) | (uint64_t(64) << 32) | (uint64_t(1) << 16);

// ---------------------------------------------------------------------------
// Scratch (device globals: allocation-free, graph-capture safe)
// ---------------------------------------------------------------------------
__device__ float          g_Q[M_TOK * D_MODEL];
__device__ float          g_K[M_TOK * D_MODEL];
__device__ float          g_V[M_TOK * D_MODEL];
__device__ float          g_X[M_TOK * D_MODEL];
__device__ __nv_bfloat16  g_act_split[(size_t)M_TOK * KPACK];   // 96 MB
__device__ __nv_bfloat16  g_w_split[(size_t)D_MODEL * KPACK];   // 6 MB

// ---------------------------------------------------------------------------
// Helpers
// ---------------------------------------------------------------------------
__device__ __forceinline__ uint32_t smem_u32(const void* p) {
    return (uint32_t)__cvta_generic_to_shared(p);
}
__device__ __forceinline__ uint32_t elect_one_pred() {
    uint32_t pred;
    asm volatile("{\n\t.reg .pred p;\n\telect.sync _|p, 0xFFFFFFFF;\n\t"
                 "selp.b32 %0, 1, 0, p;\n\t}" : "=r"(pred));
    return pred;
}
#define SWZ128(x) ((x) ^ (((x) >> 3) & 0x70))

#define MBARRIER_INIT(addr, cnt) \
    asm volatile("mbarrier.init.shared.b64 [%0], %1;" :: "r"(addr), "r"(cnt) : "memory")

#define MBARRIER_WAIT_PARITY(addr, par) do {                                      \
    uint32_t _m = (addr); uint32_t _p = (par); uint32_t _d;                       \
    asm volatile("{\n\t.reg .pred p;\n\t"                                         \
        "mbarrier.try_wait.parity.acquire.cta.shared::cta.b64 p, [%1], %2;\n\t"   \
        "selp.b32 %0, 1, 0, p;\n\t}" : "=r"(_d) : "r"(_m), "r"(_p) : "memory");   \
    if (!_d) {                                                                    \
        asm volatile("{\n\t.reg .pred P1;\n\t"                                    \
        "WL_%=:\n\t"                                                              \
        "mbarrier.try_wait.parity.acquire.cta.shared::cta.b64 P1, [%0], %1, 0x989680;\n\t" \
        "@P1 bra.uni WD_%=;\n\t"                                                  \
        "bra.uni WL_%=;\n\t"                                                      \
        "WD_%=:\n\t}" :: "r"(_m), "r"(_p) : "memory");                            \
    }                                                                             \
} while (0)

__device__ __forceinline__ void cp_async16(uint32_t dst, const void* src) {
    asm volatile("cp.async.cg.shared.global [%0], [%1], 16;"
                 :: "r"(dst), "l"(src) : "memory");
}

#if HAS_TCGEN05
#define TCGEN05_ALLOC(smem_addr, ncols) \
    asm volatile("tcgen05.alloc.cta_group::1.sync.aligned.shared::cta.b32 [%0], %1;" \
                 :: "r"(smem_addr), "r"((uint32_t)(ncols)) : "memory")
#define TCGEN05_RELINQUISH() \
    asm volatile("tcgen05.relinquish_alloc_permit.cta_group::1.sync.aligned;")
#define TCGEN05_DEALLOC(tmem, ncols) \
    asm volatile("tcgen05.dealloc.cta_group::1.sync.aligned.b32 %0, %1;" \
                 :: "r"(tmem), "r"((uint32_t)(ncols)))
#define TCGEN05_COMMIT(mbar) \
    asm volatile("tcgen05.commit.cta_group::1.mbarrier::arrive::one.shared::cluster.b64 [%0];" \
                 :: "r"(mbar) : "memory")
#define TCGEN05_FENCE_AFTER() \
    asm volatile("tcgen05.fence::after_thread_sync;" ::: "memory")
#define TCGEN05_WAIT_LD() \
    asm volatile("tcgen05.wait::ld.sync.aligned;" ::: "memory")
#define FENCE_PROXY_ASYNC() \
    asm volatile("fence.proxy.async.shared::cta;" ::: "memory")

#define TCGEN05_LD_X32(r, addr)                                              \
    asm volatile("tcgen05.ld.sync.aligned.32x32b.x32.b32 "                   \
        "{%0, %1, %2, %3, %4, %5, %6, %7, "                                  \
        " %8, %9, %10, %11, %12, %13, %14, %15, "                            \
        " %16, %17, %18, %19, %20, %21, %22, %23, "                          \
        " %24, %25, %26, %27, %28, %29, %30, %31}, [%32];"                   \
        : "=r"((r)[0]),  "=r"((r)[1]),  "=r"((r)[2]),  "=r"((r)[3]),         \
          "=r"((r)[4]),  "=r"((r)[5]),  "=r"((r)[6]),  "=r"((r)[7]),         \
          "=r"((r)[8]),  "=r"((r)[9]),  "=r"((r)[10]), "=r"((r)[11]),        \
          "=r"((r)[12]), "=r"((r)[13]), "=r"((r)[14]), "=r"((r)[15]),        \
          "=r"((r)[16]), "=r"((r)[17]), "=r"((r)[18]), "=r"((r)[19]),        \
          "=r"((r)[20]), "=r"((r)[21]), "=r"((r)[22]), "=r"((r)[23]),        \
          "=r"((r)[24]), "=r"((r)[25]), "=r"((r)[26]), "=r"((r)[27]),        \
          "=r"((r)[28]), "=r"((r)[29]), "=r"((r)[30]), "=r"((r)[31])         \
        : "r"(addr))

__device__ __forceinline__ void mma_f16_ss_cg1(uint32_t d_tmem, uint64_t adesc,
                                               uint64_t bdesc, uint32_t idesc,
                                               uint32_t enable) {
    asm volatile(
        "{\n\t.reg .pred p;\n\tsetp.ne.u32 p, %4, 0;\n\t"
        "tcgen05.mma.cta_group::1.kind::f16 [%0], %1, %2, %3, {%5,%5,%5,%5}, p;\n\t}"
        :: "r"(d_tmem), "l"(adesc), "l"(bdesc), "r"(idesc), "r"(enable), "r"(0u)
        : "memory");
}
#endif  // HAS_TCGEN05

// ---------------------------------------------------------------------------
// GEMM: C[M,1024] = Apack[M,3072] @ Bpack[1024,3072]^T + bias (fp32 out)
// Grid: (1024/BN, M/BM) = (4,128), 256 threads, dynamic smem SMEM_TOTAL.
// ---------------------------------------------------------------------------
#if HAS_TCGEN05
__device__ __forceinline__ void copy_chunk(int c, int tid, uint32_t sbase,
                                           const __nv_bfloat16* A,
                                           const __nv_bfloat16* B,
                                           int m0, int n0) {
    const uint32_t stage = (uint32_t)(c & (NSTAGE - 1)) * STAGE_BYTES;
    const char* Ab = (const char*)(A + ((size_t)m0 * KPACK + (size_t)c * CHUNK_K));
    const char* Bb = (const char*)(B + ((size_t)n0 * KPACK + (size_t)c * CHUNK_K));
#pragma unroll
    for (int j = 0; j < 12; j++) {
        int u = tid + j * 256;
        if (u < 1024) {                       // A tile: 128 rows x 8 x 16B
            int r = u >> 3, cc = u & 7;
            cp_async16(sbase + stage + SWZ128(r * 128 + cc * 16),
                       Ab + (size_t)r * (KPACK * 2) + cc * 16);
        } else {                              // B tile: 256 rows x 8 x 16B
            int v = u - 1024;
            int r = v >> 3, cc = v & 7;
            cp_async16(sbase + stage + A_STAGE_BYTES + SWZ128(r * 128 + cc * 16),
                       Bb + (size_t)r * (KPACK * 2) + cc * 16);
        }
    }
}
#endif

__global__ void __launch_bounds__(256, 1)
gemm_bf16split_bias(const __nv_bfloat16* __restrict__ A,
                    const __nv_bfloat16* __restrict__ B,
                    const float* __restrict__ bias,
                    float* __restrict__ C)
{
    extern __shared__ __align__(1024) char smem[];
    const int tid = threadIdx.x;
    const int m0 = blockIdx.y * BM;
    const int n0 = blockIdx.x * BN;

#if HAS_TCGEN05
    // ======================= tcgen05 path (sm_103a) =======================
    const uint32_t sbase = smem_u32(smem);

    if (tid == 0) {
#pragma unroll
        for (int s = 0; s < NSTAGE; s++) MBARRIER_INIT(sbase + BAR_OFF + s * 8, 1);
    }
    if (tid < 32) {
        TCGEN05_ALLOC(sbase + BAR_OFF + 40, TMEM_COLS);
        TCGEN05_RELINQUISH();
    }
    __syncthreads();
    uint32_t tmem;
    asm volatile("ld.shared.b32 %0, [%1];" : "=r"(tmem) : "r"(sbase + BAR_OFF + 40));

#pragma unroll
    for (int c = 0; c < NSTAGE - 1; c++) {
        copy_chunk(c, tid, sbase, A, B, m0, n0);
        asm volatile("cp.async.commit_group;" ::: "memory");
    }

    for (int i = 0; i < NCHUNK; i++) {
        const int c = i + NSTAGE - 1;
        if (c < NCHUNK) {
            if (c >= NSTAGE) {
                MBARRIER_WAIT_PARITY(sbase + BAR_OFF + (c & (NSTAGE - 1)) * 8,
                                     (uint32_t)(((c >> 2) - 1) & 1));
            }
            copy_chunk(c, tid, sbase, A, B, m0, n0);
            asm volatile("cp.async.commit_group;" ::: "memory");
            asm volatile("cp.async.wait_group 2;" ::: "memory");
        } else {
            asm volatile("cp.async.wait_group 0;" ::: "memory");
        }
        __syncthreads();

        if (tid < 32 && elect_one_pred()) {
            FENCE_PROXY_ASYNC();
            const uint32_t so = (uint32_t)(i & (NSTAGE - 1)) * STAGE_BYTES;
            const uint64_t ad = DESC_BASE_SW128 | (((uint64_t)((sbase + so) >> 4)) & 0x3FFF);
            const uint64_t bd = DESC_BASE_SW128 |
                                (((uint64_t)((sbase + so + A_STAGE_BYTES) >> 4)) & 0x3FFF);
#pragma unroll
            for (int k = 0; k < 4; k++)
                mma_f16_ss_cg1(tmem, ad + 2 * k, bd + 2 * k, IDESC,
                               (uint32_t)((i > 0) || (k > 0)));
            TCGEN05_COMMIT(sbase + BAR_OFF + (i & (NSTAGE - 1)) * 8);
        }
    }

    constexpr int LAST_S = (NCHUNK - 1) & (NSTAGE - 1);
    constexpr uint32_t LAST_P = ((NCHUNK - 1) / NSTAGE) & 1;
    MBARRIER_WAIT_PARITY(sbase + BAR_OFF + LAST_S * 8, LAST_P);
    TCGEN05_FENCE_AFTER();

    {
        const int w = tid >> 5, lid = tid & 31;
        const int row = (w & 3) * 32 + lid;
        const int ch  = (w >> 2) * 128;
        float* crow = C + (size_t)(m0 + row) * D_MODEL + n0;
#pragma unroll
        for (int cc = 0; cc < 4; cc++) {
            const int col0 = ch + cc * 32;
            uint32_t d[32];
            TCGEN05_LD_X32(d, tmem + col0);
            TCGEN05_WAIT_LD();
#pragma unroll
            for (int j = 0; j < 32; j += 4) {
                float4 v;
                v.x = __uint_as_float(d[j + 0]) + __ldg(bias + n0 + col0 + j + 0);
                v.y = __uint_as_float(d[j + 1]) + __ldg(bias + n0 + col0 + j + 1);
                v.z = __uint_as_float(d[j + 2]) + __ldg(bias + n0 + col0 + j + 2);
                v.w = __uint_as_float(d[j + 3]) + __ldg(bias + n0 + col0 + j + 3);
                *(float4*)(crow + col0 + j) = v;
            }
        }
    }
    __syncthreads();
    if (tid < 32) TCGEN05_DEALLOC(tmem, TMEM_COLS);

#else
    // ================== wmma bf16 fallback (plain sm_103) =================
    using namespace nvcuda;
    using FA = wmma::fragment<wmma::matrix_a, 16, 16, 16, __nv_bfloat16, wmma::row_major>;
    using FB = wmma::fragment<wmma::matrix_b, 16, 16, 16, __nv_bfloat16, wmma::col_major>;
    using FC = wmma::fragment<wmma::accumulator, 16, 16, 16, float>;

    constexpr int BKF   = 32;
    constexpr int LDF   = BKF + 8;        // 40 bf16 padded rows
    constexpr int LDCF  = 128 + 4;

    __nv_bfloat16* As = (__nv_bfloat16*)smem;            // [128][40]
    __nv_bfloat16* Bs = As + 128 * LDF;                  // [128][40]
    float*         Cs = (float*)smem;                    // reused

    const int warp = tid >> 5;
    const int wm = warp >> 1;
    const int wn = warp & 1;

    for (int half = 0; half < 2; half++) {
        const int n0h = n0 + half * 128;
        FC acc[2][4];
#pragma unroll
        for (int a = 0; a < 2; a++)
#pragma unroll
            for (int b = 0; b < 4; b++) wmma::fill_fragment(acc[a][b], 0.0f);

        for (int kt = 0; kt < KPACK; kt += BKF) {
#pragma unroll
            for (int p = 0; p < 2; p++) {
                int idx = tid + p * 256;
                int r = idx >> 2, c = idx & 3;
                *(uint4*)(As + r * LDF + c * 8) =
                    *(const uint4*)(A + (size_t)(m0 + r) * KPACK + kt + c * 8);
                *(uint4*)(Bs + r * LDF + c * 8) =
                    *(const uint4*)(B + (size_t)(n0h + r) * KPACK + kt + c * 8);
            }
            __syncthreads();
#pragma unroll
            for (int kk = 0; kk < BKF; kk += 16) {
                FA af[2];
                FB bf[4];
#pragma unroll
                for (int mi = 0; mi < 2; mi++)
                    wmma::load_matrix_sync(af[mi], As + (wm * 32 + mi * 16) * LDF + kk, LDF);
#pragma unroll
                for (int ni = 0; ni < 4; ni++)
                    wmma::load_matrix_sync(bf[ni], Bs + (wn * 64 + ni * 16) * LDF + kk, LDF);
#pragma unroll
                for (int mi = 0; mi < 2; mi++)
#pragma unroll
                    for (int ni = 0; ni < 4; ni++)
                        wmma::mma_sync(acc[mi][ni], af[mi], bf[ni], acc[mi][ni]);
            }
            __syncthreads();
        }

#pragma unroll
        for (int mi = 0; mi < 2; mi++)
#pragma unroll
            for (int ni = 0; ni < 4; ni++)
                wmma::store_matrix_sync(Cs + (wm * 32 + mi * 16) * LDCF + wn * 64 + ni * 16,
                                        acc[mi][ni], LDCF, wmma::mem_row_major);
        __syncthreads();

        const int c4 = tid & 31;
        const int r0 = tid >> 5;
        float4 bv = *(const float4*)(bias + n0h + c4 * 4);
#pragma unroll
        for (int rr = 0; rr < BM; rr += 8) {
            int r = rr + r0;
            float4 v = *(float4*)(Cs + r * LDCF + c4 * 4);
            v.x += bv.x; v.y += bv.y; v.z += bv.z; v.w += bv.w;
            *(float4*)(C + (size_t)(m0 + r) * D_MODEL + n0h + c4 * 4) = v;
        }
        __syncthreads();
    }
#endif
}

// ---------------------------------------------------------------------------
// fp32 -> 3-term bf16 split pack (out width 3072)
//   mode 0 (activation): [ hi | lo | hi ]
//   mode 1 (weight):     [ hi | hi | lo ]
// one block of 256 threads per row (4 cols per thread)
// ---------------------------------------------------------------------------
__global__ void __launch_bounds__(256)
split3_fp32_bf16(const float* __restrict__ in, __nv_bfloat16* __restrict__ out,
                 int mode)
{
    const size_t row = blockIdx.x;
    const int col = threadIdx.x * 4;
    float4 v = *(const float4*)(in + row * D_MODEL + col);

    __nv_bfloat162 h01 = __float22bfloat162_rn(make_float2(v.x, v.y));
    __nv_bfloat162 h23 = __float22bfloat162_rn(make_float2(v.z, v.w));
    float2 r01 = make_float2(v.x - __low2float(h01), v.y - __high2float(h01));
    float2 r23 = make_float2(v.z - __low2float(h23), v.w - __high2float(h23));
    __nv_bfloat162 l01 = __float22bfloat162_rn(r01);
    __nv_bfloat162 l23 = __float22bfloat162_rn(r23);

    uint2 hi, lo;
    hi.x = *(uint32_t*)&h01; hi.y = *(uint32_t*)&h23;
    lo.x = *(uint32_t*)&l01; lo.y = *(uint32_t*)&l23;

    __nv_bfloat16* o = out + row * KPACK + col;
    if (mode == 0) {          // activation: hi | lo | hi
        *(uint2*)(o)                = hi;
        *(uint2*)(o + D_MODEL)      = lo;
        *(uint2*)(o + 2 * D_MODEL)  = hi;
    } else {                  // weight: hi | hi | lo
        *(uint2*)(o)                = hi;
        *(uint2*)(o + D_MODEL)      = hi;
        *(uint2*)(o + 2 * D_MODEL)  = lo;
    }
}

// ---------------------------------------------------------------------------
// Per-token "attention" mix
// ---------------------------------------------------------------------------
__global__ void __launch_bounds__(256)
attn_mix_kernel(const float* __restrict__ Q,
                const float* __restrict__ K,
                const float* __restrict__ V,
                const int*   __restrict__ mask,
                float* __restrict__ X)
{
    __shared__ __align__(16) float qs[D_MODEL];
    __shared__ __align__(16) float vs[D_MODEL];
    __shared__ __align__(16) float kT[D_MODEL];
    __shared__ float a_s[NUM_HEADS * NUM_HEADS];

    const int t = threadIdx.x;
    const size_t base = (size_t)blockIdx.x * D_MODEL;

    float4 q4 = *(const float4*)(Q + base + t * 4);
    float4 v4 = *(const float4*)(V + base + t * 4);
    float4 k4 = *(const float4*)(K + base + t * 4);
    *(float4*)(qs + t * 4) = q4;
    *(float4*)(vs + t * 4) = v4;
    {
        int j = t * 4;
        kT[(j & 63) * 16 + (j >> 6)]             = k4.x;
        kT[((j + 1) & 63) * 16 + ((j + 1) >> 6)] = k4.y;
        kT[((j + 2) & 63) * 16 + ((j + 2) >> 6)] = k4.z;
        kT[((j + 3) & 63) * 16 + ((j + 3) >> 6)] = k4.w;
    }
    __syncthreads();

    const int i = t >> 4, l = t & 15;
    float e = 0.0f;
#pragma unroll 8
    for (int d = 0; d < HEAD_DIM; d++)
        e += qs[i * 64 + d] * kT[d * 16 + l];

    const int mk = mask[blockIdx.x];
    e = mk ? e * 0.03125f : 0.0f;

    float mx = e;
#pragma unroll
    for (int off = 8; off; off >>= 1)
        mx = fmaxf(mx, __shfl_xor_sync(0xffffffffu, mx, off, 16));
    float p = expf(e - mx);
    float s = p;
#pragma unroll
    for (int off = 8; off; off >>= 1)
        s += __shfl_xor_sync(0xffffffffu, s, off, 16);
    a_s[t] = p / s;
    __syncthreads();

#pragma unroll
    for (int r = 0; r < 4; r++) {
        int o  = r * 256 + t;
        int oi = o >> 6, od = o & 63;
        float x = 0.0f;
#pragma unroll
        for (int ll = 0; ll < 16; ll++)
            x += a_s[oi * 16 + ll] * vs[ll * 64 + od];
        X[base + o] = x;
    }
}

// ---------------------------------------------------------------------------
// Launch
// ---------------------------------------------------------------------------
extern "C" void kernel_launch(void* const* d_in, const int* in_sizes, int n_in,
                              void* d_out, int out_size)
{
    (void)in_sizes; (void)n_in; (void)out_size;
    const float* query = (const float*)d_in[0];
    const float* key   = (const float*)d_in[1];
    const float* value = (const float*)d_in[2];
    const int*   mask  = (const int*)  d_in[3];
    const float* Wq = (const float*)d_in[4];
    const float* bq = (const float*)d_in[5];
    const float* Wk = (const float*)d_in[6];
    const float* bk = (const float*)d_in[7];
    const float* Wv = (const float*)d_in[8];
    const float* bv = (const float*)d_in[9];
    const float* Wo = (const float*)d_in[10];
    const float* bo = (const float*)d_in[11];
    float* out = (float*)d_out;

    void *pQ, *pK, *pV, *pX, *pAS, *pWS;
    cudaGetSymbolAddress(&pQ, g_Q);
    cudaGetSymbolAddress(&pK, g_K);
    cudaGetSymbolAddress(&pV, g_V);
    cudaGetSymbolAddress(&pX, g_X);
    cudaGetSymbolAddress(&pAS, g_act_split);
    cudaGetSymbolAddress(&pWS, g_w_split);

    cudaFuncSetAttribute(gemm_bf16split_bias,
                         cudaFuncAttributeMaxDynamicSharedMemorySize, SMEM_TOTAL);

    __nv_bfloat16* actS = (__nv_bfloat16*)pAS;
    __nv_bfloat16* wS   = (__nv_bfloat16*)pWS;
    dim3 ggrid(D_MODEL / BN, M_TOK / BM);   // (4, 128)

    split3_fp32_bf16<<<D_MODEL, 256>>>(Wq, wS, 1);
    split3_fp32_bf16<<<M_TOK, 256>>>(query, actS, 0);
    gemm_bf16split_bias<<<ggrid, 256, SMEM_TOTAL>>>(actS, wS, bq, (float*)pQ);

    split3_fp32_bf16<<<D_MODEL, 256>>>(Wk, wS, 1);
    split3_fp32_bf16<<<M_TOK, 256>>>(key, actS, 0);
    gemm_bf16split_bias<<<ggrid, 256, SMEM_TOTAL>>>(actS, wS, bk, (float*)pK);

    split3_fp32_bf16<<<D_MODEL, 256>>>(Wv, wS, 1);
    split3_fp32_bf16<<<M_TOK, 256>>>(value, actS, 0);
    gemm_bf16split_bias<<<ggrid, 256, SMEM_TOTAL>>>(actS, wS, bv, (float*)pV);

    attn_mix_kernel<<<M_TOK, 256>>>((const float*)pQ, (const float*)pK,
                                    (const float*)pV, mask, (float*)pX);

    split3_fp32_bf16<<<D_MODEL, 256>>>(Wo, wS, 1);
    split3_fp32_bf16<<<M_TOK, 256>>>((const float*)pX, actS, 0);
    gemm_bf16split_bias<<<ggrid, 256, SMEM_TOTAL>>>(actS, wS, bo, out);
}

// round 6
// speedup vs baseline: 7.3703x; 1.2458x over previous
#include <cuda_runtime.h>
#include <cuda_bf16.h>
#include <mma.h>
#include <cstdint>

// ---------------------------------------------------------------------------
// Arch-feature gate: tcgen05 only legal in sm_103a/sm_100a PTX. The
// compute_103 (no 'a') pass compiles a correct wmma-bf16 fallback with the
// same launch geometry and math.
// ---------------------------------------------------------------------------
#if defined(__CUDA_ARCH__) && \
    (defined(__CUDA_ARCH_FEAT_SM103_ALL) || defined(__CUDA_ARCH_FEAT_SM100_ALL) || \
     (defined(__CUDA_ARCH_SPECIFIC__)        && (__CUDA_ARCH_SPECIFIC__ >= 1000)) || \
     (defined(__CUDA_ARCH_FAMILY_SPECIFIC__) && (__CUDA_ARCH_FAMILY_SPECIFIC__ >= 1000)))
#define HAS_TCGEN05 1
#else
#define HAS_TCGEN05 0
#endif

// ---------------------------------------------------------------------------
// Problem constants
// ---------------------------------------------------------------------------
constexpr int D_MODEL   = 1024;
constexpr int NUM_HEADS = 16;
constexpr int HEAD_DIM  = 64;
constexpr int M_TOK     = 16384;

// 3-term bf16 split: GEMM(K=3072) = a_hi.b_hi + a_lo.b_hi + a_hi.b_lo
//   weights packed [hi|hi|lo] width 3072; activations packed [hi|lo] width
//   2048 with logical chunk remap (chunks 32-47 re-read hi chunks 0-15).
constexpr int KW = 3 * D_MODEL;   // 3072
constexpr int KA = 2 * D_MODEL;   // 2048

// GEMM tiling (cg1, dual-M-tile): each CTA computes 256 M-rows x 256 N cols.
// Per K chunk: A0 (128x64), A1 (128x64), B (256x64) bf16 in SW128 smem.
constexpr int BMC = 256;          // M rows per CTA (two 128-row MMA tiles)
constexpr int BN  = 256;          // N per CTA
constexpr int CHUNK_K = 64;
constexpr int NCHUNK  = KW / CHUNK_K;   // 48
constexpr int NSTAGE  = 3;

constexpr int A_TILE_B  = 128 * 128;           // 16384 per A tile
constexpr int B_TILE_B  = 256 * 128;           // 32768
constexpr int STAGE_BYTES = 2 * A_TILE_B + B_TILE_B;   // 65536
constexpr int BAR_OFF   = NSTAGE * STAGE_BYTES;        // 196608
constexpr int TMEMP_OFF = BAR_OFF + 24;                // after 3 mbarriers
constexpr int SMEM_TOTAL = BAR_OFF + 32;

constexpr int TMEM_COLS = 512;    // D0: cols 0-255, D1: cols 256-511

// idesc kind::f16 cg1: dtype=F32, a/b=BF16, N=256, M=128
constexpr uint32_t IDESC =
    (1u << 4) | (1u << 7) | (1u << 10) | ((BN / 8) << 17) | ((128 / 16) << 24);

// SW128 K-major smem descriptor base (layout=SW128, version=1, SBO=64, LBO=1)
constexpr uint64_t DESC_BASE_SW128 =
    (uint64_t(2) << 61) | (uint64_t(1) << 46) | (uint64_t(64) << 32) | (uint64_t(1) << 16);

// ---------------------------------------------------------------------------
// Scratch (device globals: allocation-free, graph-capture safe)
// ---------------------------------------------------------------------------
__device__ float          g_Q[M_TOK * D_MODEL];
__device__ float          g_K[M_TOK * D_MODEL];
__device__ float          g_V[M_TOK * D_MODEL];
__device__ __nv_bfloat16  g_a0[(size_t)M_TOK * KA];   // query split / X split
__device__ __nv_bfloat16  g_a1[(size_t)M_TOK * KA];   // key split
__device__ __nv_bfloat16  g_a2[(size_t)M_TOK * KA];   // value split
__device__ __nv_bfloat16  g_w0[(size_t)D_MODEL * KW];
__device__ __nv_bfloat16  g_w1[(size_t)D_MODEL * KW];
__device__ __nv_bfloat16  g_w2[(size_t)D_MODEL * KW];
__device__ __nv_bfloat16  g_w3[(size_t)D_MODEL * KW];

// ---------------------------------------------------------------------------
// Helpers
// ---------------------------------------------------------------------------
__device__ __forceinline__ uint32_t smem_u32(const void* p) {
    return (uint32_t)__cvta_generic_to_shared(p);
}
__device__ __forceinline__ uint32_t elect_one_pred() {
    uint32_t pred;
    asm volatile("{\n\t.reg .pred p;\n\telect.sync _|p, 0xFFFFFFFF;\n\t"
                 "selp.b32 %0, 1, 0, p;\n\t}" : "=r"(pred));
    return pred;
}
#define SWZ128(x) ((x) ^ (((x) >> 3) & 0x70))

#define MBARRIER_INIT(addr, cnt) \
    asm volatile("mbarrier.init.shared.b64 [%0], %1;" :: "r"(addr), "r"((uint32_t)(cnt)) : "memory")

#define MBARRIER_WAIT_PARITY(addr, par) do {                                      \
    uint32_t _m = (addr); uint32_t _p = (par); uint32_t _d;                       \
    asm volatile("{\n\t.reg .pred p;\n\t"                                         \
        "mbarrier.try_wait.parity.acquire.cta.shared::cta.b64 p, [%1], %2;\n\t"   \
        "selp.b32 %0, 1, 0, p;\n\t}" : "=r"(_d) : "r"(_m), "r"(_p) : "memory");   \
    if (!_d) {                                                                    \
        asm volatile("{\n\t.reg .pred P1;\n\t"                                    \
        "WL_%=:\n\t"                                                              \
        "mbarrier.try_wait.parity.acquire.cta.shared::cta.b64 P1, [%0], %1, 0x989680;\n\t" \
        "@P1 bra.uni WD_%=;\n\t"                                                  \
        "bra.uni WL_%=;\n\t"                                                      \
        "WD_%=:\n\t}" :: "r"(_m), "r"(_p) : "memory");                            \
    }                                                                             \
} while (0)

__device__ __forceinline__ void cp_async16(uint32_t dst, const void* src) {
    asm volatile("cp.async.cg.shared.global [%0], [%1], 16;"
                 :: "r"(dst), "l"(src) : "memory");
}

#if HAS_TCGEN05
#define TCGEN05_ALLOC(smem_addr, ncols) \
    asm volatile("tcgen05.alloc.cta_group::1.sync.aligned.shared::cta.b32 [%0], %1;" \
                 :: "r"(smem_addr), "r"((uint32_t)(ncols)) : "memory")
#define TCGEN05_RELINQUISH() \
    asm volatile("tcgen05.relinquish_alloc_permit.cta_group::1.sync.aligned;")
#define TCGEN05_DEALLOC(tmem, ncols) \
    asm volatile("tcgen05.dealloc.cta_group::1.sync.aligned.b32 %0, %1;" \
                 :: "r"(tmem), "r"((uint32_t)(ncols)))
#define TCGEN05_COMMIT(mbar) \
    asm volatile("tcgen05.commit.cta_group::1.mbarrier::arrive::one.shared::cluster.b64 [%0];" \
                 :: "r"(mbar) : "memory")
#define TCGEN05_FENCE_AFTER() \
    asm volatile("tcgen05.fence::after_thread_sync;" ::: "memory")
#define TCGEN05_WAIT_LD() \
    asm volatile("tcgen05.wait::ld.sync.aligned;" ::: "memory")
#define FENCE_PROXY_ASYNC() \
    asm volatile("fence.proxy.async.shared::cta;" ::: "memory")

#define TCGEN05_LD_X32(r, addr)                                              \
    asm volatile("tcgen05.ld.sync.aligned.32x32b.x32.b32 "                   \
        "{%0, %1, %2, %3, %4, %5, %6, %7, "                                  \
        " %8, %9, %10, %11, %12, %13, %14, %15, "                            \
        " %16, %17, %18, %19, %20, %21, %22, %23, "                          \
        " %24, %25, %26, %27, %28, %29, %30, %31}, [%32];"                   \
        : "=r"((r)[0]),  "=r"((r)[1]),  "=r"((r)[2]),  "=r"((r)[3]),         \
          "=r"((r)[4]),  "=r"((r)[5]),  "=r"((r)[6]),  "=r"((r)[7]),         \
          "=r"((r)[8]),  "=r"((r)[9]),  "=r"((r)[10]), "=r"((r)[11]),        \
          "=r"((r)[12]), "=r"((r)[13]), "=r"((r)[14]), "=r"((r)[15]),        \
          "=r"((r)[16]), "=r"((r)[17]), "=r"((r)[18]), "=r"((r)[19]),        \
          "=r"((r)[20]), "=r"((r)[21]), "=r"((r)[22]), "=r"((r)[23]),        \
          "=r"((r)[24]), "=r"((r)[25]), "=r"((r)[26]), "=r"((r)[27]),        \
          "=r"((r)[28]), "=r"((r)[29]), "=r"((r)[30]), "=r"((r)[31])         \
        : "r"(addr))

__device__ __forceinline__ void mma_f16_ss_cg1(uint32_t d_tmem, uint64_t adesc,
                                               uint64_t bdesc, uint32_t idesc,
                                               uint32_t enable) {
    asm volatile(
        "{\n\t.reg .pred p;\n\tsetp.ne.u32 p, %4, 0;\n\t"
        "tcgen05.mma.cta_group::1.kind::f16 [%0], %1, %2, %3, {%5,%5,%5,%5}, p;\n\t}"
        :: "r"(d_tmem), "l"(adesc), "l"(bdesc), "r"(idesc), "r"(enable), "r"(0u)
        : "memory");
}

// Per chunk: A0 (128x64 from rows m0), A1 (rows m0+128), B (256x64).
__device__ __forceinline__ void copy_chunk(int c, int tid, uint32_t sbase,
                                           const __nv_bfloat16* A,
                                           const __nv_bfloat16* B,
                                           int m0, int n0) {
    const uint32_t stage = (uint32_t)(c % NSTAGE) * STAGE_BYTES;
    const int ca = (c < 32) ? c : (c - 32);      // activation hi-chunk reuse
    const char* Ab = (const char*)(A + (size_t)m0 * KA + (size_t)ca * CHUNK_K);
    const char* Bb = (const char*)(B + (size_t)n0 * KW + (size_t)c * CHUNK_K);
#pragma unroll
    for (int j = 0; j < 16; j++) {
        int u = tid + j * 256;                   // 0..4095 (16B units)
        if (u < 2048) {                          // A0 | A1
            int r = u >> 3, cc = u & 7;          // r in 0..255
            cp_async16(sbase + stage + ((r >> 7) ? A_TILE_B : 0)
                           + SWZ128((r & 127) * 128 + cc * 16),
                       Ab + (size_t)r * (KA * 2) + cc * 16);
        } else {                                 // B: 256 rows
            int v = u - 2048;
            int r = v >> 3, cc = v & 7;
            cp_async16(sbase + stage + 2 * A_TILE_B + SWZ128(r * 128 + cc * 16),
                       Bb + (size_t)r * (KW * 2) + cc * 16);
        }
    }
}
#endif  // HAS_TCGEN05

// ---------------------------------------------------------------------------
// GEMM core: C[m0..m0+256, n0..n0+256] = A[.,remap(3072)] @ W[.,3072]^T + bias
// ---------------------------------------------------------------------------
__device__ __forceinline__ void gemm_core(const __nv_bfloat16* __restrict__ A,
                                          const __nv_bfloat16* __restrict__ B,
                                          const float* __restrict__ bias,
                                          float* __restrict__ C,
                                          char* smem)
{
    const int tid = threadIdx.x;
    const int m0 = blockIdx.y * BMC;
    const int n0 = blockIdx.x * BN;

#if HAS_TCGEN05
    const uint32_t sbase = smem_u32(smem);

    if (tid == 0) {
#pragma unroll
        for (int s = 0; s < NSTAGE; s++) MBARRIER_INIT(sbase + BAR_OFF + s * 8, 1);
    }
    if (tid < 32) {
        TCGEN05_ALLOC(sbase + TMEMP_OFF, TMEM_COLS);
        TCGEN05_RELINQUISH();
    }
    __syncthreads();
    uint32_t tmem;
    asm volatile("ld.shared.b32 %0, [%1];" : "=r"(tmem) : "r"(sbase + TMEMP_OFF));

#pragma unroll
    for (int c = 0; c < NSTAGE - 1; c++) {
        copy_chunk(c, tid, sbase, A, B, m0, n0);
        asm volatile("cp.async.commit_group;" ::: "memory");
    }

    for (int i = 0; i < NCHUNK; i++) {
        const int c = i + NSTAGE - 1;
        if (c < NCHUNK) {
            if (c >= NSTAGE) {   // stage reused from chunk c-NSTAGE
                MBARRIER_WAIT_PARITY(sbase + BAR_OFF + (c % NSTAGE) * 8,
                                     (uint32_t)(((c / NSTAGE) - 1) & 1));
            }
            copy_chunk(c, tid, sbase, A, B, m0, n0);
            asm volatile("cp.async.commit_group;" ::: "memory");
            asm volatile("cp.async.wait_group 1;" ::: "memory");   // NSTAGE-2
        } else {
            asm volatile("cp.async.wait_group 0;" ::: "memory");
        }
        __syncthreads();

        if (tid < 32 && elect_one_pred()) {
            FENCE_PROXY_ASYNC();
            const uint32_t so = (uint32_t)(i % NSTAGE) * STAGE_BYTES;
            const uint64_t a0d = DESC_BASE_SW128 | (((uint64_t)((sbase + so) >> 4)) & 0x3FFF);
            const uint64_t a1d = DESC_BASE_SW128 |
                                 (((uint64_t)((sbase + so + A_TILE_B) >> 4)) & 0x3FFF);
            const uint64_t bd  = DESC_BASE_SW128 |
                                 (((uint64_t)((sbase + so + 2 * A_TILE_B) >> 4)) & 0x3FFF);
            const uint32_t en0 = (uint32_t)(i > 0);
#pragma unroll
            for (int k = 0; k < 4; k++) {
                mma_f16_ss_cg1(tmem,       a0d + 2 * k, bd + 2 * k, IDESC, en0 | (k > 0));
                mma_f16_ss_cg1(tmem + 256, a1d + 2 * k, bd + 2 * k, IDESC, en0 | (k > 0));
            }
            TCGEN05_COMMIT(sbase + BAR_OFF + (i % NSTAGE) * 8);
        }
    }

    constexpr int LAST_S = (NCHUNK - 1) % NSTAGE;                  // 2
    constexpr uint32_t LAST_P = ((NCHUNK - 1) / NSTAGE) & 1;       // 1
    MBARRIER_WAIT_PARITY(sbase + BAR_OFF + LAST_S * 8, LAST_P);
    TCGEN05_FENCE_AFTER();

    {   // epilogue: warps 0-3 -> D0 (rows m0+), warps 4-7 -> D1 (rows m0+128+)
        const int w = tid >> 5, lid = tid & 31;
        const int half = w >> 2;
        const int row  = (w & 3) * 32 + lid;
        const uint32_t dbase = tmem + half * 256;
        float* crow = C + (size_t)(m0 + half * 128 + row) * D_MODEL + n0;
#pragma unroll
        for (int cc = 0; cc < 8; cc++) {
            const int col0 = cc * 32;
            uint32_t d[32];
            TCGEN05_LD_X32(d, dbase + col0);
            TCGEN05_WAIT_LD();
#pragma unroll
            for (int j = 0; j < 32; j += 4) {
                float4 v;
                v.x = __uint_as_float(d[j + 0]) + __ldg(bias + n0 + col0 + j + 0);
                v.y = __uint_as_float(d[j + 1]) + __ldg(bias + n0 + col0 + j + 1);
                v.z = __uint_as_float(d[j + 2]) + __ldg(bias + n0 + col0 + j + 2);
                v.w = __uint_as_float(d[j + 3]) + __ldg(bias + n0 + col0 + j + 3);
                *(float4*)(crow + col0 + j) = v;
            }
        }
    }
    __syncthreads();
    if (tid < 32) TCGEN05_DEALLOC(tmem, TMEM_COLS);

#else
    // ================== wmma bf16 fallback (plain sm_103) =================
    using namespace nvcuda;
    using FA = wmma::fragment<wmma::matrix_a, 16, 16, 16, __nv_bfloat16, wmma::row_major>;
    using FB = wmma::fragment<wmma::matrix_b, 16, 16, 16, __nv_bfloat16, wmma::col_major>;
    using FC = wmma::fragment<wmma::accumulator, 16, 16, 16, float>;

    constexpr int BKF  = 32;
    constexpr int LDF  = BKF + 8;
    constexpr int LDCF = 128 + 4;

    __nv_bfloat16* As = (__nv_bfloat16*)smem;
    __nv_bfloat16* Bs = As + 128 * LDF;
    float*         Cs = (float*)smem;

    const int warp = tid >> 5;
    const int wm = warp >> 1;
    const int wn = warp & 1;

    for (int mt = 0; mt < 2; mt++) {
        const int m0h = m0 + mt * 128;
        for (int half = 0; half < 2; half++) {
            const int n0h = n0 + half * 128;
            FC acc[2][4];
#pragma unroll
            for (int a = 0; a < 2; a++)
#pragma unroll
                for (int b = 0; b < 4; b++) wmma::fill_fragment(acc[a][b], 0.0f);

            for (int kt = 0; kt < KW; kt += BKF) {
                const int ka = (kt < KA) ? kt : (kt - KA);
#pragma unroll
                for (int p = 0; p < 2; p++) {
                    int idx = tid + p * 256;
                    int r = idx >> 2, cidx = idx & 3;
                    *(uint4*)(As + r * LDF + cidx * 8) =
                        *(const uint4*)(A + (size_t)(m0h + r) * KA + ka + cidx * 8);
                    *(uint4*)(Bs + r * LDF + cidx * 8) =
                        *(const uint4*)(B + (size_t)(n0h + r) * KW + kt + cidx * 8);
                }
                __syncthreads();
#pragma unroll
                for (int kk = 0; kk < BKF; kk += 16) {
                    FA af[2];
                    FB bf[4];
#pragma unroll
                    for (int mi = 0; mi < 2; mi++)
                        wmma::load_matrix_sync(af[mi], As + (wm * 32 + mi * 16) * LDF + kk, LDF);
#pragma unroll
                    for (int ni = 0; ni < 4; ni++)
                        wmma::load_matrix_sync(bf[ni], Bs + (wn * 64 + ni * 16) * LDF + kk, LDF);
#pragma unroll
                    for (int mi = 0; mi < 2; mi++)
#pragma unroll
                        for (int ni = 0; ni < 4; ni++)
                            wmma::mma_sync(acc[mi][ni], af[mi], bf[ni], acc[mi][ni]);
                }
                __syncthreads();
            }

#pragma unroll
            for (int mi = 0; mi < 2; mi++)
#pragma unroll
                for (int ni = 0; ni < 4; ni++)
                    wmma::store_matrix_sync(Cs + (wm * 32 + mi * 16) * LDCF + wn * 64 + ni * 16,
                                            acc[mi][ni], LDCF, wmma::mem_row_major);
            __syncthreads();

            const int c4 = tid & 31;
            const int r0 = tid >> 5;
            float4 bv = *(const float4*)(bias + n0h + c4 * 4);
#pragma unroll
            for (int rr = 0; rr < 128; rr += 8) {
                int r = rr + r0;
                float4 v = *(float4*)(Cs + r * LDCF + c4 * 4);
                v.x += bv.x; v.y += bv.y; v.z += bv.z; v.w += bv.w;
                *(float4*)(C + (size_t)(m0h + r) * D_MODEL + n0h + c4 * 4) = v;
            }
            __syncthreads();
        }
    }
#endif
}

// Fused QKV GEMM: blockIdx.z selects (A, W, bias, C) triple.  grid (4,64,3)
__global__ void __launch_bounds__(256, 1)
gemm_qkv(const __nv_bfloat16* __restrict__ a0, const __nv_bfloat16* __restrict__ a1,
         const __nv_bfloat16* __restrict__ a2,
         const __nv_bfloat16* __restrict__ w0, const __nv_bfloat16* __restrict__ w1,
         const __nv_bfloat16* __restrict__ w2,
         const float* __restrict__ bq, const float* __restrict__ bk,
         const float* __restrict__ bv,
         float* __restrict__ cq, float* __restrict__ ck, float* __restrict__ cv)
{
    extern __shared__ __align__(1024) char smem[];
    const int z = blockIdx.z;
    const __nv_bfloat16* A = (z == 0) ? a0 : (z == 1) ? a1 : a2;
    const __nv_bfloat16* W = (z == 0) ? w0 : (z == 1) ? w1 : w2;
    const float* bias      = (z == 0) ? bq : (z == 1) ? bk : bv;
    float* C               = (z == 0) ? cq : (z == 1) ? ck : cv;
    gemm_core(A, W, bias, C, smem);
}

// Single GEMM (output projection).  grid (4,64)
__global__ void __launch_bounds__(256, 1)
gemm_one(const __nv_bfloat16* __restrict__ A, const __nv_bfloat16* __restrict__ W,
         const float* __restrict__ bias, float* __restrict__ C)
{
    extern __shared__ __align__(1024) char smem[];
    gemm_core(A, W, bias, C, smem);
}

// ---------------------------------------------------------------------------
// Fused splits
// ---------------------------------------------------------------------------
__device__ __forceinline__ void split_row4(float4 v, uint2& hi, uint2& lo) {
    __nv_bfloat162 h01 = __float22bfloat162_rn(make_float2(v.x, v.y));
    __nv_bfloat162 h23 = __float22bfloat162_rn(make_float2(v.z, v.w));
    float2 r01 = make_float2(v.x - __low2float(h01), v.y - __high2float(h01));
    float2 r23 = make_float2(v.z - __low2float(h23), v.w - __high2float(h23));
    __nv_bfloat162 l01 = __float22bfloat162_rn(r01);
    __nv_bfloat162 l23 = __float22bfloat162_rn(r23);
    hi.x = *(uint32_t*)&h01; hi.y = *(uint32_t*)&h23;
    lo.x = *(uint32_t*)&l01; lo.y = *(uint32_t*)&l23;
}

// acts: 3 tensors -> [hi|lo] width 2048.  grid = 3*16384
__global__ void __launch_bounds__(256)
act_split3(const float* __restrict__ q, const float* __restrict__ k,
           const float* __restrict__ v,
           __nv_bfloat16* __restrict__ oq, __nv_bfloat16* __restrict__ ok,
           __nv_bfloat16* __restrict__ ov)
{
    const int b = blockIdx.x;
    const int which = b >> 14;
    const size_t row = (size_t)(b & 16383);
    const float* in = (which == 0) ? q : (which == 1) ? k : v;
    __nv_bfloat16* out = (which == 0) ? oq : (which == 1) ? ok : ov;

    const int col = threadIdx.x * 4;
    uint2 hi, lo;
    split_row4(*(const float4*)(in + row * D_MODEL + col), hi, lo);
    *(uint2*)(out + row * KA + col)           = hi;
    *(uint2*)(out + row * KA + D_MODEL + col) = lo;
}

// weights: 4 tensors -> [hi|hi|lo] width 3072.  grid = 4*1024
__global__ void __launch_bounds__(256)
w_split4(const float* __restrict__ w0, const float* __restrict__ w1,
         const float* __restrict__ w2, const float* __restrict__ w3,
         __nv_bfloat16* __restrict__ o0, __nv_bfloat16* __restrict__ o1,
         __nv_bfloat16* __restrict__ o2, __nv_bfloat16* __restrict__ o3)
{
    const int b = blockIdx.x;
    const int which = b >> 10;
    const size_t row = (size_t)(b & 1023);
    const float* in = (which == 0) ? w0 : (which == 1) ? w1 : (which == 2) ? w2 : w3;
    __nv_bfloat16* out = (which == 0) ? o0 : (which == 1) ? o1 : (which == 2) ? o2 : o3;

    const int col = threadIdx.x * 4;
    uint2 hi, lo;
    split_row4(*(const float4*)(in + row * D_MODEL + col), hi, lo);
    __nv_bfloat16* o = out + row * KW + col;
    *(uint2*)(o)                = hi;
    *(uint2*)(o + D_MODEL)      = hi;
    *(uint2*)(o + 2 * D_MODEL)  = lo;
}

// ---------------------------------------------------------------------------
// Per-token "attention" mix; writes X directly as [hi|lo] bf16 split.
// kT XOR-swizzled (l ^ (d>>2)): 2-way store conflicts instead of 16-way.
// ---------------------------------------------------------------------------
__global__ void __launch_bounds__(256)
attn_mix_split(const float* __restrict__ Q,
               const float* __restrict__ K,
               const float* __restrict__ V,
               const int*   __restrict__ mask,
               __nv_bfloat16* __restrict__ Xs)
{
    __shared__ __align__(16) float qs[D_MODEL];
    __shared__ __align__(16) float vs[D_MODEL];
    __shared__ __align__(16) float kT[D_MODEL];   // kT[d*16 + (l ^ (d>>2))]
    __shared__ float a_s[NUM_HEADS * NUM_HEADS];

    const int t = threadIdx.x;
    const size_t base = (size_t)blockIdx.x * D_MODEL;

    float4 q4 = *(const float4*)(Q + base + t * 4);
    float4 v4 = *(const float4*)(V + base + t * 4);
    float4 k4 = *(const float4*)(K + base + t * 4);
    *(float4*)(qs + t * 4) = q4;
    *(float4*)(vs + t * 4) = v4;
    {
        int j = t * 4;
        int d0 = j & 63, l0 = j >> 6;     // j multiple of 4: d0..d0+3 share l
        int x = l0 ^ (d0 >> 2);
        kT[(d0 + 0) * 16 + x] = k4.x;
        kT[(d0 + 1) * 16 + x] = k4.y;
        kT[(d0 + 2) * 16 + x] = k4.z;
        kT[(d0 + 3) * 16 + x] = k4.w;
    }
    __syncthreads();

    const int i = t >> 4, l = t & 15;
    float e = 0.0f;
#pragma unroll
    for (int d = 0; d < HEAD_DIM; d += 4) {
        float4 qv = *(const float4*)(qs + i * 64 + d);
        int x = l ^ (d >> 2);
        e += qv.x * kT[(d + 0) * 16 + x];
        e += qv.y * kT[(d + 1) * 16 + x];
        e += qv.z * kT[(d + 2) * 16 + x];
        e += qv.w * kT[(d + 3) * 16 + x];
    }

    const int mk = mask[blockIdx.x];
    e = mk ? e * 0.03125f : 0.0f;         // 1/sqrt(1024); masked -> uniform

    float mx = e;
#pragma unroll
    for (int off = 8; off; off >>= 1)
        mx = fmaxf(mx, __shfl_xor_sync(0xffffffffu, mx, off, 16));
    float p = expf(e - mx);
    float s = p;
#pragma unroll
    for (int off = 8; off; off >>= 1)
        s += __shfl_xor_sync(0xffffffffu, s, off, 16);
    a_s[t] = p / s;
    __syncthreads();

    const size_t obase = (size_t)blockIdx.x * KA;
#pragma unroll
    for (int r = 0; r < 4; r++) {
        int o  = r * 256 + t;
        int oi = o >> 6, od = o & 63;
        float x = 0.0f;
#pragma unroll
        for (int ll = 0; ll < 16; ll++)
            x += a_s[oi * 16 + ll] * vs[ll * 64 + od];
        __nv_bfloat16 h = __float2bfloat16(x);
        __nv_bfloat16 lo = __float2bfloat16(x - __bfloat162float(h));
        Xs[obase + o]           = h;
        Xs[obase + D_MODEL + o] = lo;
    }
}

// ---------------------------------------------------------------------------
// Launch
// ---------------------------------------------------------------------------
extern "C" void kernel_launch(void* const* d_in, const int* in_sizes, int n_in,
                              void* d_out, int out_size)
{
    (void)in_sizes; (void)n_in; (void)out_size;
    const float* query = (const float*)d_in[0];
    const float* key   = (const float*)d_in[1];
    const float* value = (const float*)d_in[2];
    const int*   mask  = (const int*)  d_in[3];
    const float* Wq = (const float*)d_in[4];
    const float* bq = (const float*)d_in[5];
    const float* Wk = (const float*)d_in[6];
    const float* bk = (const float*)d_in[7];
    const float* Wv = (const float*)d_in[8];
    const float* bv = (const float*)d_in[9];
    const float* Wo = (const float*)d_in[10];
    const float* bo = (const float*)d_in[11];
    float* out = (float*)d_out;

    void *pQ, *pK, *pV, *pA0, *pA1, *pA2, *pW0, *pW1, *pW2, *pW3;
    cudaGetSymbolAddress(&pQ, g_Q);
    cudaGetSymbolAddress(&pK, g_K);
    cudaGetSymbolAddress(&pV, g_V);
    cudaGetSymbolAddress(&pA0, g_a0);
    cudaGetSymbolAddress(&pA1, g_a1);
    cudaGetSymbolAddress(&pA2, g_a2);
    cudaGetSymbolAddress(&pW0, g_w0);
    cudaGetSymbolAddress(&pW1, g_w1);
    cudaGetSymbolAddress(&pW2, g_w2);
    cudaGetSymbolAddress(&pW3, g_w3);

    cudaFuncSetAttribute(gemm_qkv,
                         cudaFuncAttributeMaxDynamicSharedMemorySize, SMEM_TOTAL);
    cudaFuncSetAttribute(gemm_one,
                         cudaFuncAttributeMaxDynamicSharedMemorySize, SMEM_TOTAL);

    w_split4<<<4096, 256>>>(Wq, Wk, Wv, Wo,
                            (__nv_bfloat16*)pW0, (__nv_bfloat16*)pW1,
                            (__nv_bfloat16*)pW2, (__nv_bfloat16*)pW3);
    act_split3<<<3 * M_TOK, 256>>>(query, key, value,
                                   (__nv_bfloat16*)pA0, (__nv_bfloat16*)pA1,
                                   (__nv_bfloat16*)pA2);

    dim3 qkvgrid(D_MODEL / BN, M_TOK / BMC, 3);   // (4, 64, 3)
    gemm_qkv<<<qkvgrid, 256, SMEM_TOTAL>>>(
        (__nv_bfloat16*)pA0, (__nv_bfloat16*)pA1, (__nv_bfloat16*)pA2,
        (__nv_bfloat16*)pW0, (__nv_bfloat16*)pW1, (__nv_bfloat16*)pW2,
        bq, bk, bv, (float*)pQ, (float*)pK, (float*)pV);

    // per-token head-mix; writes X split directly into pA0 (reused)
    attn_mix_split<<<M_TOK, 256>>>((const float*)pQ, (const float*)pK,
                                   (const float*)pV, mask, (__nv_bfloat16*)pA0);

    dim3 ogrid(D_MODEL / BN, M_TOK / BMC);        // (4, 64)
    gemm_one<<<ogrid, 256, SMEM_TOTAL>>>((__nv_bfloat16*)pA0,
                                         (__nv_bfloat16*)pW3, bo, out);
}